// round 1
// baseline (speedup 1.0000x reference)
#include <cuda_runtime.h>

// Problem constants (fixed by the dataset): N=100000 nodes, E=1000000 edges, F=64 feats.
#define NMAX 100000
#define FEAT 64
#define FEAT4 16

// Scratch (device globals — no allocation allowed in kernel_launch)
__device__ int   g_cnt1[NMAX];
__device__ int   g_cnt2[NMAX];
__device__ float g_inv1[NMAX];
__device__ float g_inv2[NMAX];
__device__ float g_inv3[NMAX];
__device__ float g_agg[(size_t)NMAX * FEAT];
__device__ float g_h1 [(size_t)NMAX * FEAT];
__device__ float g_h2 [(size_t)NMAX * FEAT];

// ---------------------------------------------------------------------------
// Degree kernels
// ---------------------------------------------------------------------------
__global__ void zero_counts_kernel(int n) {
    int i = blockIdx.x * blockDim.x + threadIdx.x;
    if (i < n) { g_cnt1[i] = 0; g_cnt2[i] = 0; }
}

__global__ void count_deg_kernel(const int* __restrict__ src,
                                 const int* __restrict__ dst, int e) {
    int i = blockIdx.x * blockDim.x + threadIdx.x;
    if (i < e) {
        atomicAdd(&g_cnt1[src[i]], 1);
        atomicAdd(&g_cnt2[dst[i]], 1);
    }
}

__global__ void finalize_inv_kernel(int n) {
    int i = blockIdx.x * blockDim.x + threadIdx.x;
    if (i < n) {
        int c1 = g_cnt1[i];
        int c2 = g_cnt2[i];
        g_inv1[i] = 1.0f / (float)(c1 > 0 ? c1 : 1);
        g_inv2[i] = 1.0f / (float)(c2 > 0 ? c2 : 1);
        int c3 = c1 + c2;
        g_inv3[i] = 1.0f / (float)(c3 > 0 ? c3 : 1);
    }
}

// ---------------------------------------------------------------------------
// Zero the aggregation buffer (float4 stores)
// ---------------------------------------------------------------------------
__global__ void zero_agg_kernel(int n16) {
    int i = blockIdx.x * blockDim.x + threadIdx.x;
    if (i < n16) {
        ((float4*)g_agg)[i] = make_float4(0.f, 0.f, 0.f, 0.f);
    }
}

// ---------------------------------------------------------------------------
// Edge aggregation: agg[d] += x[s] * inv[s]
// 16 threads per edge, one float4 each; scatter via red.global.add.v4.f32
// ---------------------------------------------------------------------------
__global__ void aggregate_kernel(const float4* __restrict__ x,
                                 const int* __restrict__ s,
                                 const int* __restrict__ d,
                                 const float* __restrict__ inv,
                                 int e) {
    int idx = blockIdx.x * blockDim.x + threadIdx.x;
    int total = e << 4;
    if (idx >= total) return;
    int ei = idx >> 4;
    int f  = idx & 15;
    int sv = __ldg(s + ei);
    int dv = __ldg(d + ei);
    float iw = __ldg(inv + sv);
    float4 v = __ldg(x + (size_t)sv * FEAT4 + f);
    v.x *= iw; v.y *= iw; v.z *= iw; v.w *= iw;
    float* p = g_agg + ((size_t)dv * FEAT + f * 4);
    asm volatile("red.global.add.v4.f32 [%0], {%1, %2, %3, %4};"
                 :: "l"(p), "f"(v.x), "f"(v.y), "f"(v.z), "f"(v.w)
                 : "memory");
}

// ---------------------------------------------------------------------------
// Fused concat-GEMM + bias + optional ReLU:
//   out[row] = act( [x[row], agg[row]] @ W + b ),  W: [128, 64] row-major
// One thread per row; W + b staged in shared (broadcast LDS reads).
// ---------------------------------------------------------------------------
__global__ void __launch_bounds__(128)
sage_gemm_kernel(const float4* __restrict__ x,
                 const float4* __restrict__ agg,
                 const float*  __restrict__ W,
                 const float*  __restrict__ b,
                 float* __restrict__ out,
                 int n, int relu) {
    __shared__ float4 Ws[128 * FEAT4];   // 128 rows x 64 cols = 2048 float4 (32 KB)
    __shared__ float  bs[FEAT];

    int tid = threadIdx.x;
    const float4* W4 = (const float4*)W;
    #pragma unroll
    for (int i = 0; i < 16; i++)
        Ws[tid + 128 * i] = W4[tid + 128 * i];
    if (tid < FEAT) bs[tid] = b[tid];
    __syncthreads();

    int row = blockIdx.x * 128 + tid;
    if (row >= n) return;

    float4 acc[FEAT4];
    #pragma unroll
    for (int j = 0; j < FEAT4; j++)
        acc[j] = make_float4(bs[4 * j], bs[4 * j + 1], bs[4 * j + 2], bs[4 * j + 3]);

    #pragma unroll
    for (int half = 0; half < 2; half++) {
        const float4* in = (half == 0) ? (x + (size_t)row * FEAT4)
                                       : (agg + (size_t)row * FEAT4);
        const float4* wbase = Ws + half * 64 * FEAT4;
        #pragma unroll 1
        for (int k4 = 0; k4 < 16; k4++) {
            float4 xv = __ldg(in + k4);
            const float4* wr = wbase + k4 * 4 * FEAT4;
            #pragma unroll
            for (int c = 0; c < 4; c++) {
                float sc = (c == 0) ? xv.x : (c == 1) ? xv.y : (c == 2) ? xv.z : xv.w;
                #pragma unroll
                for (int j = 0; j < FEAT4; j++) {
                    float4 w = wr[c * FEAT4 + j];
                    acc[j].x += sc * w.x;
                    acc[j].y += sc * w.y;
                    acc[j].z += sc * w.z;
                    acc[j].w += sc * w.w;
                }
            }
        }
    }

    float4* o = (float4*)(out + (size_t)row * FEAT);
    #pragma unroll
    for (int j = 0; j < FEAT4; j++) {
        float4 v = acc[j];
        if (relu) {
            v.x = fmaxf(v.x, 0.f); v.y = fmaxf(v.y, 0.f);
            v.z = fmaxf(v.z, 0.f); v.w = fmaxf(v.w, 0.f);
        }
        o[j] = v;
    }
}

// ---------------------------------------------------------------------------
// Launch
// ---------------------------------------------------------------------------
extern "C" void kernel_launch(void* const* d_in, const int* in_sizes, int n_in,
                              void* d_out, int out_size) {
    const float* x   = (const float*)d_in[0];
    const int*   src = (const int*)  d_in[1];
    const int*   dst = (const int*)  d_in[2];
    const float* W1  = (const float*)d_in[3];
    const float* b1  = (const float*)d_in[4];
    const float* W2  = (const float*)d_in[5];
    const float* b2  = (const float*)d_in[6];
    const float* W3  = (const float*)d_in[7];
    const float* b3  = (const float*)d_in[8];
    float* out = (float*)d_out;

    int n = in_sizes[0] / FEAT;   // 100000
    int e = in_sizes[1];          // 1000000

    // Device-global scratch addresses
    void *p_agg, *p_h1, *p_h2, *p_inv1, *p_inv2, *p_inv3;
    cudaGetSymbolAddress(&p_agg,  g_agg);
    cudaGetSymbolAddress(&p_h1,   g_h1);
    cudaGetSymbolAddress(&p_h2,   g_h2);
    cudaGetSymbolAddress(&p_inv1, g_inv1);
    cudaGetSymbolAddress(&p_inv2, g_inv2);
    cudaGetSymbolAddress(&p_inv3, g_inv3);
    float4* agg4 = (float4*)p_agg;
    float*  aggf = (float*)p_agg;
    float*  h1   = (float*)p_h1;
    float*  h2   = (float*)p_h2;

    const int TB = 256;
    int nb_n   = (n + TB - 1) / TB;
    int nb_e   = (e + TB - 1) / TB;
    int n16    = n * FEAT4;                 // float4 count of agg
    int nb_z   = (n16 + TB - 1) / TB;
    int et     = e << 4;                    // threads for aggregation
    int nb_agg = (et + TB - 1) / TB;
    int nb_g   = (n + 127) / 128;           // gemm blocks

    // Degrees (all three directions in one edge pass)
    zero_counts_kernel<<<nb_n, TB>>>(n);
    count_deg_kernel<<<nb_e, TB>>>(src, dst, e);
    finalize_inv_kernel<<<nb_n, TB>>>(n);

    // Layer 1: 'O' (src -> dst), ReLU
    zero_agg_kernel<<<nb_z, TB>>>(n16);
    aggregate_kernel<<<nb_agg, TB>>>((const float4*)x, src, dst, (const float*)p_inv1, e);
    sage_gemm_kernel<<<nb_g, 128>>>((const float4*)x, agg4, W1, b1, h1, n, 1);

    // Layer 2: 'I' (dst -> src, reversed graph), ReLU
    zero_agg_kernel<<<nb_z, TB>>>(n16);
    aggregate_kernel<<<nb_agg, TB>>>((const float4*)h1, dst, src, (const float*)p_inv2, e);
    sage_gemm_kernel<<<nb_g, 128>>>((const float4*)h1, agg4, W2, b2, h2, n, 1);

    // Layer 3: 'U' (undirected = both directions, deg = in+out), no activation
    zero_agg_kernel<<<nb_z, TB>>>(n16);
    aggregate_kernel<<<nb_agg, TB>>>((const float4*)h2, src, dst, (const float*)p_inv3, e);
    aggregate_kernel<<<nb_agg, TB>>>((const float4*)h2, dst, src, (const float*)p_inv3, e);
    sage_gemm_kernel<<<nb_g, 128>>>((const float4*)h2, agg4, W3, b3, out, n, 0);

    (void)n_in; (void)out_size; (void)aggf;
}

// round 3
// speedup vs baseline: 1.2132x; 1.2132x over previous
#include <cuda_runtime.h>

// Problem constants (fixed by the dataset): N=100000 nodes, E=1000000 edges, F=64.
#define NMAX 100000
#define EMAX 1000000
#define FEAT 64
#define FEAT4 16
#define SCAN_B 1024
#define NBLK_SCAN ((NMAX + SCAN_B - 1) / SCAN_B)   // 98

// ---------------------------------------------------------------------------
// Device-global scratch (no allocation allowed)
// ---------------------------------------------------------------------------
__device__ int   g_cnt_out[NMAX];   // out-degree (by src)
__device__ int   g_cnt_in [NMAX];   // in-degree  (by dst)
__device__ float g_inv1[NMAX];      // 1/max(out,1)
__device__ float g_inv2[NMAX];      // 1/max(in,1)
__device__ float g_inv3[NMAX];      // 1/max(in+out,1)
__device__ int   g_start_in [NMAX];
__device__ int   g_start_out[NMAX];
__device__ int   g_cur_in [NMAX];
__device__ int   g_cur_out[NMAX];
__device__ int   g_bsum_in [NBLK_SCAN + 1];
__device__ int   g_bsum_out[NBLK_SCAN + 1];
__device__ int   g_in_list [EMAX];  // grouped by dst, stores src
__device__ int   g_out_list[EMAX];  // grouped by src, stores dst
__device__ float g_agg[(size_t)NMAX * FEAT];
__device__ float g_h1 [(size_t)NMAX * FEAT];
__device__ float g_h2 [(size_t)NMAX * FEAT];

// ---------------------------------------------------------------------------
// Degree + CSR build
// ---------------------------------------------------------------------------
__global__ void zero_counts_kernel(int n) {
    int i = blockIdx.x * blockDim.x + threadIdx.x;
    if (i < n) { g_cnt_out[i] = 0; g_cnt_in[i] = 0; }
}

__global__ void count_deg_kernel(const int* __restrict__ src,
                                 const int* __restrict__ dst, int e) {
    int i = blockIdx.x * blockDim.x + threadIdx.x;
    if (i < e) {
        atomicAdd(&g_cnt_out[src[i]], 1);
        atomicAdd(&g_cnt_in [dst[i]], 1);
    }
}

__global__ void finalize_inv_kernel(int n) {
    int i = blockIdx.x * blockDim.x + threadIdx.x;
    if (i < n) {
        int co = g_cnt_out[i];
        int ci = g_cnt_in[i];
        g_inv1[i] = 1.0f / (float)(co > 0 ? co : 1);
        g_inv2[i] = 1.0f / (float)(ci > 0 ? ci : 1);
        int cu = co + ci;
        g_inv3[i] = 1.0f / (float)(cu > 0 ? cu : 1);
    }
}

// Hillis-Steele block-exclusive scan; emits per-block totals.
__global__ void scan_block_kernel(const int* __restrict__ in,
                                  int* __restrict__ out,
                                  int* __restrict__ bsums, int n) {
    __shared__ int sh[SCAN_B];
    int tid = threadIdx.x;
    int gid = blockIdx.x * SCAN_B + tid;
    int v = (gid < n) ? in[gid] : 0;
    sh[tid] = v;
    __syncthreads();
    int acc = v;
    #pragma unroll
    for (int off = 1; off < SCAN_B; off <<= 1) {
        int add = (tid >= off) ? sh[tid - off] : 0;
        __syncthreads();
        acc += add;
        sh[tid] = acc;
        __syncthreads();
    }
    if (gid < n) out[gid] = acc - v;          // exclusive
    if (tid == SCAN_B - 1) bsums[blockIdx.x] = acc;
}

__global__ void scan_sums_kernel(int* __restrict__ b1, int* __restrict__ b2, int nb) {
    if (threadIdx.x == 0) {
        int acc = 0;
        for (int i = 0; i < nb; i++) { int t = b1[i]; b1[i] = acc; acc += t; }
    } else if (threadIdx.x == 1) {
        int acc = 0;
        for (int i = 0; i < nb; i++) { int t = b2[i]; b2[i] = acc; acc += t; }
    }
}

__global__ void add_offsets_kernel(int n) {
    int gid = blockIdx.x * SCAN_B + threadIdx.x;
    if (gid < n) {
        int si = g_start_in[gid]  + g_bsum_in [blockIdx.x];
        int so = g_start_out[gid] + g_bsum_out[blockIdx.x];
        g_start_in[gid]  = si;  g_cur_in[gid]  = si;
        g_start_out[gid] = so;  g_cur_out[gid] = so;
    }
}

__global__ void fill_lists_kernel(const int* __restrict__ src,
                                  const int* __restrict__ dst, int e) {
    int i = blockIdx.x * blockDim.x + threadIdx.x;
    if (i < e) {
        int s = src[i], d = dst[i];
        int p1 = atomicAdd(&g_cur_in[d], 1);
        g_in_list[p1] = s;
        int p2 = atomicAdd(&g_cur_out[s], 1);
        g_out_list[p2] = d;
    }
}

// ---------------------------------------------------------------------------
// Gather aggregation: agg[i] = sum over list[i] of x[s] * inv[s]
// 16 threads per node, one float4 feature slice each. No atomics, no zeroing.
// ---------------------------------------------------------------------------
__global__ void __launch_bounds__(256)
gather_agg_kernel(const float4* __restrict__ x,
                  const int* __restrict__ list,
                  const int* __restrict__ start,
                  const int* __restrict__ cnt,
                  const float* __restrict__ inv,
                  float4* __restrict__ agg, int n) {
    int t = blockIdx.x * blockDim.x + threadIdx.x;
    int node = t >> 4, f = t & 15;
    if (node >= n) return;
    int base = start[node];
    int deg  = cnt[node];
    float4 acc = make_float4(0.f, 0.f, 0.f, 0.f);
    #pragma unroll 2
    for (int j = 0; j < deg; j++) {
        int s = __ldg(list + base + j);
        float iw = __ldg(inv + s);
        float4 v = __ldg(x + (size_t)s * FEAT4 + f);
        acc.x += v.x * iw; acc.y += v.y * iw;
        acc.z += v.z * iw; acc.w += v.w * iw;
    }
    agg[(size_t)node * FEAT4 + f] = acc;
}

// Layer 3 (undirected): both in- and out-lists, scaled by inv3[source].
__global__ void __launch_bounds__(256)
gather_agg_undirected_kernel(const float4* __restrict__ x,
                             const float* __restrict__ inv,
                             float4* __restrict__ agg, int n) {
    int t = blockIdx.x * blockDim.x + threadIdx.x;
    int node = t >> 4, f = t & 15;
    if (node >= n) return;
    float4 acc = make_float4(0.f, 0.f, 0.f, 0.f);
    {
        int base = g_start_in[node];
        int deg  = g_cnt_in[node];
        #pragma unroll 2
        for (int j = 0; j < deg; j++) {
            int s = __ldg(g_in_list + base + j);
            float iw = __ldg(inv + s);
            float4 v = __ldg(x + (size_t)s * FEAT4 + f);
            acc.x += v.x * iw; acc.y += v.y * iw;
            acc.z += v.z * iw; acc.w += v.w * iw;
        }
    }
    {
        int base = g_start_out[node];
        int deg  = g_cnt_out[node];
        #pragma unroll 2
        for (int j = 0; j < deg; j++) {
            int s = __ldg(g_out_list + base + j);
            float iw = __ldg(inv + s);
            float4 v = __ldg(x + (size_t)s * FEAT4 + f);
            acc.x += v.x * iw; acc.y += v.y * iw;
            acc.z += v.z * iw; acc.w += v.w * iw;
        }
    }
    agg[(size_t)node * FEAT4 + f] = acc;
}

// ---------------------------------------------------------------------------
// Fused concat-GEMM + bias + optional ReLU using packed fma.rn.f32x2.
//   out[row] = act( [x[row], agg[row]] @ W + b ),  W: [128, 64] row-major
// ---------------------------------------------------------------------------
__device__ __forceinline__ void fma2(unsigned long long& d,
                                     unsigned long long a,
                                     unsigned long long b) {
    asm("fma.rn.f32x2 %0, %1, %2, %0;" : "+l"(d) : "l"(a), "l"(b));
}
__device__ __forceinline__ unsigned long long pack2(float lo, float hi) {
    unsigned long long r;
    asm("mov.b64 %0, {%1, %2};" : "=l"(r) : "f"(lo), "f"(hi));
    return r;
}
__device__ __forceinline__ void unpack2(unsigned long long v, float& lo, float& hi) {
    asm("mov.b64 {%0, %1}, %2;" : "=f"(lo), "=f"(hi) : "l"(v));
}

__global__ void __launch_bounds__(128)
sage_gemm_kernel(const float4* __restrict__ x,
                 const float4* __restrict__ agg,
                 const float*  __restrict__ W,
                 const float*  __restrict__ b,
                 float* __restrict__ out,
                 int n, int relu) {
    __shared__ float4 Ws[128 * FEAT4];   // [k=128][col4=16] -> 32 KB
    __shared__ float  bs[FEAT];

    int tid = threadIdx.x;
    const float4* W4 = (const float4*)W;
    #pragma unroll
    for (int i = 0; i < 16; i++)
        Ws[tid + 128 * i] = W4[tid + 128 * i];
    if (tid < FEAT) bs[tid] = b[tid];
    __syncthreads();

    int row = blockIdx.x * 128 + tid;
    if (row >= n) return;

    unsigned long long acc[32];          // 64 outputs as 32 f32x2 pairs
    #pragma unroll
    for (int j = 0; j < 32; j++)
        acc[j] = pack2(bs[2 * j], bs[2 * j + 1]);

    #pragma unroll
    for (int half = 0; half < 2; half++) {
        const float4* in = (half == 0) ? (x + (size_t)row * FEAT4)
                                       : (agg + (size_t)row * FEAT4);
        const float4* wbase = Ws + half * 64 * FEAT4;
        #pragma unroll 1
        for (int k4 = 0; k4 < 16; k4++) {
            float4 xv = __ldg(in + k4);
            const float4* wr = wbase + k4 * 4 * FEAT4;
            #pragma unroll
            for (int c = 0; c < 4; c++) {
                float sc = (c == 0) ? xv.x : (c == 1) ? xv.y : (c == 2) ? xv.z : xv.w;
                unsigned long long s2 = pack2(sc, sc);
                const ulonglong2* wr2 = (const ulonglong2*)(wr + c * FEAT4);
                #pragma unroll
                for (int j = 0; j < 16; j++) {
                    ulonglong2 w = wr2[j];
                    fma2(acc[2 * j],     s2, w.x);
                    fma2(acc[2 * j + 1], s2, w.y);
                }
            }
        }
    }

    float4* o = (float4*)(out + (size_t)row * FEAT);
    #pragma unroll
    for (int j4 = 0; j4 < FEAT4; j4++) {
        float4 v;
        unpack2(acc[2 * j4],     v.x, v.y);
        unpack2(acc[2 * j4 + 1], v.z, v.w);
        if (relu) {
            v.x = fmaxf(v.x, 0.f); v.y = fmaxf(v.y, 0.f);
            v.z = fmaxf(v.z, 0.f); v.w = fmaxf(v.w, 0.f);
        }
        o[j4] = v;
    }
}

// ---------------------------------------------------------------------------
// Launch
// ---------------------------------------------------------------------------
extern "C" void kernel_launch(void* const* d_in, const int* in_sizes, int n_in,
                              void* d_out, int out_size) {
    const float* x   = (const float*)d_in[0];
    const int*   src = (const int*)  d_in[1];
    const int*   dst = (const int*)  d_in[2];
    const float* W1  = (const float*)d_in[3];
    const float* b1  = (const float*)d_in[4];
    const float* W2  = (const float*)d_in[5];
    const float* b2  = (const float*)d_in[6];
    const float* W3  = (const float*)d_in[7];
    const float* b3  = (const float*)d_in[8];
    float* out = (float*)d_out;

    int n = in_sizes[0] / FEAT;   // 100000
    int e = in_sizes[1];          // 1000000

    void *p_agg, *p_h1, *p_h2, *p_inv1, *p_inv2, *p_inv3;
    void *p_cnt_in, *p_cnt_out, *p_start_in, *p_start_out;
    void *p_bsum_in, *p_bsum_out, *p_in_list, *p_out_list;
    cudaGetSymbolAddress(&p_agg,       g_agg);
    cudaGetSymbolAddress(&p_h1,        g_h1);
    cudaGetSymbolAddress(&p_h2,        g_h2);
    cudaGetSymbolAddress(&p_inv1,      g_inv1);
    cudaGetSymbolAddress(&p_inv2,      g_inv2);
    cudaGetSymbolAddress(&p_inv3,      g_inv3);
    cudaGetSymbolAddress(&p_cnt_in,    g_cnt_in);
    cudaGetSymbolAddress(&p_cnt_out,   g_cnt_out);
    cudaGetSymbolAddress(&p_start_in,  g_start_in);
    cudaGetSymbolAddress(&p_start_out, g_start_out);
    cudaGetSymbolAddress(&p_bsum_in,   g_bsum_in);
    cudaGetSymbolAddress(&p_bsum_out,  g_bsum_out);
    cudaGetSymbolAddress(&p_in_list,   g_in_list);
    cudaGetSymbolAddress(&p_out_list,  g_out_list);

    float4* agg4 = (float4*)p_agg;
    float*  h1   = (float*)p_h1;
    float*  h2   = (float*)p_h2;

    const int TB = 256;
    int nb_n   = (n + TB - 1) / TB;
    int nb_e   = (e + TB - 1) / TB;
    int nb_s   = (n + SCAN_B - 1) / SCAN_B;
    int gt     = n << 4;                    // 16 threads per node
    int nb_g16 = (gt + TB - 1) / TB;
    int nb_g   = (n + 127) / 128;

    // --- CSR build (graph shared by all layers) ---
    zero_counts_kernel<<<nb_n, TB>>>(n);
    count_deg_kernel<<<nb_e, TB>>>(src, dst, e);
    finalize_inv_kernel<<<nb_n, TB>>>(n);
    scan_block_kernel<<<nb_s, SCAN_B>>>((const int*)p_cnt_in,  (int*)p_start_in,  (int*)p_bsum_in,  n);
    scan_block_kernel<<<nb_s, SCAN_B>>>((const int*)p_cnt_out, (int*)p_start_out, (int*)p_bsum_out, n);
    scan_sums_kernel<<<1, 32>>>((int*)p_bsum_in, (int*)p_bsum_out, nb_s);
    add_offsets_kernel<<<nb_s, SCAN_B>>>(n);
    fill_lists_kernel<<<nb_e, TB>>>(src, dst, e);

    // --- Layer 1: 'O' (aggregate at dst over in-edges, scale 1/out-deg[src]) ---
    gather_agg_kernel<<<nb_g16, TB>>>((const float4*)x, (const int*)p_in_list,
                                      (const int*)p_start_in, (const int*)p_cnt_in,
                                      (const float*)p_inv1, agg4, n);
    sage_gemm_kernel<<<nb_g, 128>>>((const float4*)x, agg4, W1, b1, h1, n, 1);

    // --- Layer 2: 'I' (reversed: aggregate at src over out-edges, scale 1/in-deg[dst]) ---
    gather_agg_kernel<<<nb_g16, TB>>>((const float4*)h1, (const int*)p_out_list,
                                      (const int*)p_start_out, (const int*)p_cnt_out,
                                      (const float*)p_inv2, agg4, n);
    sage_gemm_kernel<<<nb_g, 128>>>((const float4*)h1, agg4, W2, b2, h2, n, 1);

    // --- Layer 3: 'U' (undirected: both lists, scale 1/(in+out)[source]) ---
    gather_agg_undirected_kernel<<<nb_g16, TB>>>((const float4*)h2,
                                                 (const float*)p_inv3, agg4, n);
    sage_gemm_kernel<<<nb_g, 128>>>((const float4*)h2, agg4, W3, b3, out, n, 0);

    (void)n_in; (void)out_size;
}

// round 4
// speedup vs baseline: 1.4059x; 1.1588x over previous
#include <cuda_runtime.h>

// Problem constants: N=100000 nodes, E=1000000 edges, F=64.
#define NMAX 100000
#define EMAX 1000000
#define FEAT 64
#define FEAT4 16
#define SCAN_B 1024
#define NBLK_SCAN ((NMAX + SCAN_B - 1) / SCAN_B)   // 98

// ---------------------------------------------------------------------------
// Device-global scratch
// ---------------------------------------------------------------------------
__device__ int   g_cnt_out[NMAX];
__device__ int   g_cnt_in [NMAX];
__device__ float g_inv1[NMAX];
__device__ float g_inv2[NMAX];
__device__ float g_inv3[NMAX];
__device__ int   g_start_in [NMAX];
__device__ int   g_start_out[NMAX];
__device__ int   g_cur_in [NMAX];
__device__ int   g_cur_out[NMAX];
__device__ int   g_bsum_in [NBLK_SCAN + 1];
__device__ int   g_bsum_out[NBLK_SCAN + 1];
__device__ int   g_in_list [EMAX];
__device__ int   g_out_list[EMAX];
__device__ float g_agg[(size_t)NMAX * FEAT];
__device__ float g_h1 [(size_t)NMAX * FEAT];
__device__ float g_h2 [(size_t)NMAX * FEAT];

// ---------------------------------------------------------------------------
// Degree + CSR build
// ---------------------------------------------------------------------------
__global__ void zero_counts_kernel(int n) {
    int i = blockIdx.x * blockDim.x + threadIdx.x;
    if (i < n) { g_cnt_out[i] = 0; g_cnt_in[i] = 0; }
}

__global__ void count_deg_kernel(const int* __restrict__ src,
                                 const int* __restrict__ dst, int e) {
    int i = blockIdx.x * blockDim.x + threadIdx.x;
    if (i < e) {
        atomicAdd(&g_cnt_out[src[i]], 1);
        atomicAdd(&g_cnt_in [dst[i]], 1);
    }
}

__global__ void finalize_inv_kernel(int n) {
    int i = blockIdx.x * blockDim.x + threadIdx.x;
    if (i < n) {
        int co = g_cnt_out[i];
        int ci = g_cnt_in[i];
        g_inv1[i] = 1.0f / (float)(co > 0 ? co : 1);
        g_inv2[i] = 1.0f / (float)(ci > 0 ? ci : 1);
        int cu = co + ci;
        g_inv3[i] = 1.0f / (float)(cu > 0 ? cu : 1);
    }
}

// Dual-array block scan: blockIdx.y selects (cnt_in -> start_in, bsum_in)
// or (cnt_out -> start_out, bsum_out).
__global__ void scan_block2_kernel(int n) {
    __shared__ int sh[SCAN_B];
    const int* in  = (blockIdx.y == 0) ? g_cnt_in  : g_cnt_out;
    int* out   = (blockIdx.y == 0) ? g_start_in : g_start_out;
    int* bsums = (blockIdx.y == 0) ? g_bsum_in  : g_bsum_out;
    int tid = threadIdx.x;
    int gid = blockIdx.x * SCAN_B + tid;
    int v = (gid < n) ? in[gid] : 0;
    sh[tid] = v;
    __syncthreads();
    int acc = v;
    #pragma unroll
    for (int off = 1; off < SCAN_B; off <<= 1) {
        int add = (tid >= off) ? sh[tid - off] : 0;
        __syncthreads();
        acc += add;
        sh[tid] = acc;
        __syncthreads();
    }
    if (gid < n) out[gid] = acc - v;
    if (tid == SCAN_B - 1) bsums[blockIdx.x] = acc;
}

// Parallel scan of block sums (nb <= 128), blockIdx.x selects array.
__global__ void scan_sums_kernel(int nb) {
    __shared__ int sh[128];
    int* b = (blockIdx.x == 0) ? g_bsum_in : g_bsum_out;
    int tid = threadIdx.x;
    int v = (tid < nb) ? b[tid] : 0;
    sh[tid] = v;
    __syncthreads();
    int acc = v;
    #pragma unroll
    for (int off = 1; off < 128; off <<= 1) {
        int add = (tid >= off) ? sh[tid - off] : 0;
        __syncthreads();
        acc += add;
        sh[tid] = acc;
        __syncthreads();
    }
    if (tid < nb) b[tid] = acc - v;   // exclusive
}

__global__ void add_offsets_kernel(int n) {
    int gid = blockIdx.x * SCAN_B + threadIdx.x;
    if (gid < n) {
        int si = g_start_in[gid]  + g_bsum_in [blockIdx.x];
        int so = g_start_out[gid] + g_bsum_out[blockIdx.x];
        g_start_in[gid]  = si;  g_cur_in[gid]  = si;
        g_start_out[gid] = so;  g_cur_out[gid] = so;
    }
}

__global__ void fill_lists_kernel(const int* __restrict__ src,
                                  const int* __restrict__ dst, int e) {
    int i = blockIdx.x * blockDim.x + threadIdx.x;
    if (i < e) {
        int s = src[i], d = dst[i];
        int p1 = atomicAdd(&g_cur_in[d], 1);
        g_in_list[p1] = s;
        int p2 = atomicAdd(&g_cur_out[s], 1);
        g_out_list[p2] = d;
    }
}

// ---------------------------------------------------------------------------
// Gather aggregation. 8 lanes per node, 2 float4 per lane.
// Edges processed in explicit batches of 4 -> 4 idx + 4 inv + 8 x loads in flight.
// ---------------------------------------------------------------------------
__device__ __forceinline__ void acc_edge(const float4* __restrict__ x,
                                         int s, float iw, int f2,
                                         float4& a0, float4& a1) {
    float4 v0 = __ldg(x + (size_t)s * FEAT4 + f2);
    float4 v1 = __ldg(x + (size_t)s * FEAT4 + f2 + 1);
    a0.x += v0.x * iw; a0.y += v0.y * iw; a0.z += v0.z * iw; a0.w += v0.w * iw;
    a1.x += v1.x * iw; a1.y += v1.y * iw; a1.z += v1.z * iw; a1.w += v1.w * iw;
}

__device__ __forceinline__ void gather_range(const float4* __restrict__ x,
                                             const int* __restrict__ list,
                                             const float* __restrict__ inv,
                                             int base, int deg, int f2,
                                             float4& a0, float4& a1) {
    int j = 0;
    for (; j + 4 <= deg; j += 4) {
        int s0 = __ldg(list + base + j);
        int s1 = __ldg(list + base + j + 1);
        int s2 = __ldg(list + base + j + 2);
        int s3 = __ldg(list + base + j + 3);
        float w0 = __ldg(inv + s0);
        float w1 = __ldg(inv + s1);
        float w2 = __ldg(inv + s2);
        float w3 = __ldg(inv + s3);
        acc_edge(x, s0, w0, f2, a0, a1);
        acc_edge(x, s1, w1, f2, a0, a1);
        acc_edge(x, s2, w2, f2, a0, a1);
        acc_edge(x, s3, w3, f2, a0, a1);
    }
    for (; j < deg; j++) {
        int s = __ldg(list + base + j);
        float w = __ldg(inv + s);
        acc_edge(x, s, w, f2, a0, a1);
    }
}

__global__ void __launch_bounds__(256)
gather_agg_kernel(const float4* __restrict__ x,
                  const int* __restrict__ list,
                  const int* __restrict__ start,
                  const int* __restrict__ cnt,
                  const float* __restrict__ inv,
                  float4* __restrict__ agg, int n) {
    int t = blockIdx.x * blockDim.x + threadIdx.x;
    int node = t >> 3, f2 = (t & 7) * 2;
    if (node >= n) return;
    float4 a0 = make_float4(0.f, 0.f, 0.f, 0.f);
    float4 a1 = make_float4(0.f, 0.f, 0.f, 0.f);
    gather_range(x, list, inv, start[node], cnt[node], f2, a0, a1);
    agg[(size_t)node * FEAT4 + f2]     = a0;
    agg[(size_t)node * FEAT4 + f2 + 1] = a1;
}

__global__ void __launch_bounds__(256)
gather_agg_undirected_kernel(const float4* __restrict__ x,
                             const float* __restrict__ inv,
                             float4* __restrict__ agg, int n) {
    int t = blockIdx.x * blockDim.x + threadIdx.x;
    int node = t >> 3, f2 = (t & 7) * 2;
    if (node >= n) return;
    float4 a0 = make_float4(0.f, 0.f, 0.f, 0.f);
    float4 a1 = make_float4(0.f, 0.f, 0.f, 0.f);
    gather_range(x, g_in_list,  inv, g_start_in[node],  g_cnt_in[node],  f2, a0, a1);
    gather_range(x, g_out_list, inv, g_start_out[node], g_cnt_out[node], f2, a0, a1);
    agg[(size_t)node * FEAT4 + f2]     = a0;
    agg[(size_t)node * FEAT4 + f2 + 1] = a1;
}

// ---------------------------------------------------------------------------
// Fused concat-GEMM + bias + optional ReLU. Packed fma.rn.f32x2,
// 2 rows per thread so each W shared-load feeds 4 FFMA2s.
// ---------------------------------------------------------------------------
__device__ __forceinline__ void fma2(unsigned long long& d,
                                     unsigned long long a,
                                     unsigned long long b) {
    asm("fma.rn.f32x2 %0, %1, %2, %0;" : "+l"(d) : "l"(a), "l"(b));
}
__device__ __forceinline__ unsigned long long pack2(float lo, float hi) {
    unsigned long long r;
    asm("mov.b64 %0, {%1, %2};" : "=l"(r) : "f"(lo), "f"(hi));
    return r;
}
__device__ __forceinline__ void unpack2(unsigned long long v, float& lo, float& hi) {
    asm("mov.b64 {%0, %1}, %2;" : "=f"(lo), "=f"(hi) : "l"(v));
}

__global__ void __launch_bounds__(128)
sage_gemm_kernel(const float4* __restrict__ x,
                 const float4* __restrict__ agg,
                 const float*  __restrict__ W,
                 const float*  __restrict__ b,
                 float* __restrict__ out,
                 int n, int relu) {
    __shared__ float4 Ws[128 * FEAT4];   // [k=128][col4=16] -> 32 KB
    __shared__ float  bs[FEAT];

    int tid = threadIdx.x;
    const float4* W4 = (const float4*)W;
    #pragma unroll
    for (int i = 0; i < 16; i++)
        Ws[tid + 128 * i] = W4[tid + 128 * i];
    if (tid < FEAT) bs[tid] = b[tid];
    __syncthreads();

    int r0 = blockIdx.x * 256 + tid;
    int r1 = r0 + 128;
    bool has0 = (r0 < n), has1 = (r1 < n);
    if (!has0) return;

    unsigned long long accA[32], accB[32];
    #pragma unroll
    for (int j = 0; j < 32; j++) {
        accA[j] = pack2(bs[2 * j], bs[2 * j + 1]);
        accB[j] = accA[j];
    }

    #pragma unroll
    for (int half = 0; half < 2; half++) {
        const float4* inA = (half == 0) ? (x + (size_t)r0 * FEAT4)
                                        : (agg + (size_t)r0 * FEAT4);
        const float4* inB = (half == 0) ? (x + (size_t)r1 * FEAT4)
                                        : (agg + (size_t)r1 * FEAT4);
        const float4* wbase = Ws + half * 64 * FEAT4;
        #pragma unroll 1
        for (int k4 = 0; k4 < 16; k4++) {
            float4 xa = __ldg(inA + k4);
            float4 xb = has1 ? __ldg(inB + k4) : make_float4(0.f, 0.f, 0.f, 0.f);
            const float4* wr = wbase + k4 * 4 * FEAT4;
            #pragma unroll
            for (int c = 0; c < 4; c++) {
                float sa = (c == 0) ? xa.x : (c == 1) ? xa.y : (c == 2) ? xa.z : xa.w;
                float sb = (c == 0) ? xb.x : (c == 1) ? xb.y : (c == 2) ? xb.z : xb.w;
                unsigned long long sa2 = pack2(sa, sa);
                unsigned long long sb2 = pack2(sb, sb);
                const ulonglong2* wr2 = (const ulonglong2*)(wr + c * FEAT4);
                #pragma unroll
                for (int j = 0; j < 16; j++) {
                    ulonglong2 w = wr2[j];
                    fma2(accA[2 * j],     sa2, w.x);
                    fma2(accA[2 * j + 1], sa2, w.y);
                    fma2(accB[2 * j],     sb2, w.x);
                    fma2(accB[2 * j + 1], sb2, w.y);
                }
            }
        }
    }

    {
        float4* o = (float4*)(out + (size_t)r0 * FEAT);
        #pragma unroll
        for (int j4 = 0; j4 < FEAT4; j4++) {
            float4 v;
            unpack2(accA[2 * j4],     v.x, v.y);
            unpack2(accA[2 * j4 + 1], v.z, v.w);
            if (relu) {
                v.x = fmaxf(v.x, 0.f); v.y = fmaxf(v.y, 0.f);
                v.z = fmaxf(v.z, 0.f); v.w = fmaxf(v.w, 0.f);
            }
            o[j4] = v;
        }
    }
    if (has1) {
        float4* o = (float4*)(out + (size_t)r1 * FEAT);
        #pragma unroll
        for (int j4 = 0; j4 < FEAT4; j4++) {
            float4 v;
            unpack2(accB[2 * j4],     v.x, v.y);
            unpack2(accB[2 * j4 + 1], v.z, v.w);
            if (relu) {
                v.x = fmaxf(v.x, 0.f); v.y = fmaxf(v.y, 0.f);
                v.z = fmaxf(v.z, 0.f); v.w = fmaxf(v.w, 0.f);
            }
            o[j4] = v;
        }
    }
}

// ---------------------------------------------------------------------------
// Launch
// ---------------------------------------------------------------------------
extern "C" void kernel_launch(void* const* d_in, const int* in_sizes, int n_in,
                              void* d_out, int out_size) {
    const float* x   = (const float*)d_in[0];
    const int*   src = (const int*)  d_in[1];
    const int*   dst = (const int*)  d_in[2];
    const float* W1  = (const float*)d_in[3];
    const float* b1  = (const float*)d_in[4];
    const float* W2  = (const float*)d_in[5];
    const float* b2  = (const float*)d_in[6];
    const float* W3  = (const float*)d_in[7];
    const float* b3  = (const float*)d_in[8];
    float* out = (float*)d_out;

    int n = in_sizes[0] / FEAT;   // 100000
    int e = in_sizes[1];          // 1000000

    void *p_agg, *p_h1, *p_h2, *p_inv1, *p_inv2, *p_inv3;
    void *p_cnt_in, *p_cnt_out, *p_start_in, *p_start_out;
    void *p_in_list, *p_out_list;
    cudaGetSymbolAddress(&p_agg,       g_agg);
    cudaGetSymbolAddress(&p_h1,        g_h1);
    cudaGetSymbolAddress(&p_h2,        g_h2);
    cudaGetSymbolAddress(&p_inv1,      g_inv1);
    cudaGetSymbolAddress(&p_inv2,      g_inv2);
    cudaGetSymbolAddress(&p_inv3,      g_inv3);
    cudaGetSymbolAddress(&p_cnt_in,    g_cnt_in);
    cudaGetSymbolAddress(&p_cnt_out,   g_cnt_out);
    cudaGetSymbolAddress(&p_start_in,  g_start_in);
    cudaGetSymbolAddress(&p_start_out, g_start_out);
    cudaGetSymbolAddress(&p_in_list,   g_in_list);
    cudaGetSymbolAddress(&p_out_list,  g_out_list);

    float4* agg4 = (float4*)p_agg;
    float*  h1   = (float*)p_h1;
    float*  h2   = (float*)p_h2;

    const int TB = 256;
    int nb_n   = (n + TB - 1) / TB;
    int nb_e   = (e + TB - 1) / TB;
    int nb_s   = (n + SCAN_B - 1) / SCAN_B;
    int gt     = n << 3;                    // 8 threads per node
    int nb_g8  = (gt + TB - 1) / TB;
    int nb_g   = (n + 255) / 256;           // 2 rows/thread, 128 threads

    // --- CSR build ---
    zero_counts_kernel<<<nb_n, TB>>>(n);
    count_deg_kernel<<<nb_e, TB>>>(src, dst, e);
    finalize_inv_kernel<<<nb_n, TB>>>(n);
    {
        dim3 g(nb_s, 2);
        scan_block2_kernel<<<g, SCAN_B>>>(n);
    }
    scan_sums_kernel<<<2, 128>>>(nb_s);
    add_offsets_kernel<<<nb_s, SCAN_B>>>(n);
    fill_lists_kernel<<<nb_e, TB>>>(src, dst, e);

    // --- Layer 1: 'O' ---
    gather_agg_kernel<<<nb_g8, TB>>>((const float4*)x, (const int*)p_in_list,
                                     (const int*)p_start_in, (const int*)p_cnt_in,
                                     (const float*)p_inv1, agg4, n);
    sage_gemm_kernel<<<nb_g, 128>>>((const float4*)x, agg4, W1, b1, h1, n, 1);

    // --- Layer 2: 'I' ---
    gather_agg_kernel<<<nb_g8, TB>>>((const float4*)h1, (const int*)p_out_list,
                                     (const int*)p_start_out, (const int*)p_cnt_out,
                                     (const float*)p_inv2, agg4, n);
    sage_gemm_kernel<<<nb_g, 128>>>((const float4*)h1, agg4, W2, b2, h2, n, 1);

    // --- Layer 3: 'U' ---
    gather_agg_undirected_kernel<<<nb_g8, TB>>>((const float4*)h2,
                                                (const float*)p_inv3, agg4, n);
    sage_gemm_kernel<<<nb_g, 128>>>((const float4*)h2, agg4, W3, b3, out, n, 0);

    (void)n_in; (void)out_size;
}

// round 5
// speedup vs baseline: 1.4228x; 1.0120x over previous
#include <cuda_runtime.h>

// Problem constants: N=100000 nodes, E=1000000 edges, F=64.
#define NMAX 100000
#define EMAX 1000000
#define FEAT 64
#define FEAT4 16
#define SCAN_B 1024
#define NBLK_SCAN ((NMAX + SCAN_B - 1) / SCAN_B)   // 98

// ---------------------------------------------------------------------------
// Device-global scratch
// ---------------------------------------------------------------------------
__device__ int   g_cnt_out[NMAX];
__device__ int   g_cnt_in [NMAX];
__device__ float g_inv1[NMAX];
__device__ float g_inv2[NMAX];
__device__ float g_inv3[NMAX];
__device__ int   g_start_in [NMAX];
__device__ int   g_start_out[NMAX];
__device__ int   g_cur_in [NMAX];
__device__ int   g_cur_out[NMAX];
__device__ int   g_bsum_in [NBLK_SCAN + 1];
__device__ int   g_bsum_out[NBLK_SCAN + 1];
__device__ int   g_in_list [EMAX];
__device__ int   g_out_list[EMAX];
__device__ float g_agg[(size_t)NMAX * FEAT];
__device__ float g_h1 [(size_t)NMAX * FEAT];
__device__ float g_h2 [(size_t)NMAX * FEAT];

// ---------------------------------------------------------------------------
// Degree + CSR build
// ---------------------------------------------------------------------------
__global__ void count_deg_kernel(const int* __restrict__ src,
                                 const int* __restrict__ dst, int e) {
    int i = blockIdx.x * blockDim.x + threadIdx.x;
    if (i < e) {
        atomicAdd(&g_cnt_out[src[i]], 1);
        atomicAdd(&g_cnt_in [dst[i]], 1);
    }
}

// Dual-array block scan: blockIdx.y selects (cnt_in -> start_in, bsum_in)
// or (cnt_out -> start_out, bsum_out).
__global__ void scan_block2_kernel(int n) {
    __shared__ int sh[SCAN_B];
    const int* in  = (blockIdx.y == 0) ? g_cnt_in  : g_cnt_out;
    int* out   = (blockIdx.y == 0) ? g_start_in : g_start_out;
    int* bsums = (blockIdx.y == 0) ? g_bsum_in  : g_bsum_out;
    int tid = threadIdx.x;
    int gid = blockIdx.x * SCAN_B + tid;
    int v = (gid < n) ? in[gid] : 0;
    sh[tid] = v;
    __syncthreads();
    int acc = v;
    #pragma unroll
    for (int off = 1; off < SCAN_B; off <<= 1) {
        int add = (tid >= off) ? sh[tid - off] : 0;
        __syncthreads();
        acc += add;
        sh[tid] = acc;
        __syncthreads();
    }
    if (gid < n) out[gid] = acc - v;
    if (tid == SCAN_B - 1) bsums[blockIdx.x] = acc;
}

// Parallel scan of block sums (nb <= 128), blockIdx.x selects array.
__global__ void scan_sums_kernel(int nb) {
    __shared__ int sh[128];
    int* b = (blockIdx.x == 0) ? g_bsum_in : g_bsum_out;
    int tid = threadIdx.x;
    int v = (tid < nb) ? b[tid] : 0;
    sh[tid] = v;
    __syncthreads();
    int acc = v;
    #pragma unroll
    for (int off = 1; off < 128; off <<= 1) {
        int add = (tid >= off) ? sh[tid - off] : 0;
        __syncthreads();
        acc += add;
        sh[tid] = acc;
        __syncthreads();
    }
    if (tid < nb) b[tid] = acc - v;   // exclusive
}

// Adds block offsets AND computes the three inverse-degree arrays (cnt hot in L2).
__global__ void add_offsets_inv_kernel(int n) {
    int gid = blockIdx.x * SCAN_B + threadIdx.x;
    if (gid < n) {
        int si = g_start_in[gid]  + g_bsum_in [blockIdx.x];
        int so = g_start_out[gid] + g_bsum_out[blockIdx.x];
        g_start_in[gid]  = si;  g_cur_in[gid]  = si;
        g_start_out[gid] = so;  g_cur_out[gid] = so;
        int co = g_cnt_out[gid];
        int ci = g_cnt_in[gid];
        g_inv1[gid] = 1.0f / (float)(co > 0 ? co : 1);
        g_inv2[gid] = 1.0f / (float)(ci > 0 ? ci : 1);
        int cu = co + ci;
        g_inv3[gid] = 1.0f / (float)(cu > 0 ? cu : 1);
    }
}

__global__ void fill_lists_kernel(const int* __restrict__ src,
                                  const int* __restrict__ dst, int e) {
    int i = blockIdx.x * blockDim.x + threadIdx.x;
    if (i < e) {
        int s = src[i], d = dst[i];
        int p1 = atomicAdd(&g_cur_in[d], 1);
        g_in_list[p1] = s;
        int p2 = atomicAdd(&g_cur_out[s], 1);
        g_out_list[p2] = d;
    }
}

// ---------------------------------------------------------------------------
// Gather aggregation. 8 lanes per node, 2 float4 per lane.
// Edges processed in batches of 8 -> 8 idx + 8 inv + 16 x loads in flight.
// ---------------------------------------------------------------------------
__device__ __forceinline__ void acc_edge(const float4* __restrict__ x,
                                         int s, float iw, int f2,
                                         float4& a0, float4& a1) {
    float4 v0 = __ldg(x + (size_t)s * FEAT4 + f2);
    float4 v1 = __ldg(x + (size_t)s * FEAT4 + f2 + 1);
    a0.x += v0.x * iw; a0.y += v0.y * iw; a0.z += v0.z * iw; a0.w += v0.w * iw;
    a1.x += v1.x * iw; a1.y += v1.y * iw; a1.z += v1.z * iw; a1.w += v1.w * iw;
}

__device__ __forceinline__ void gather_range(const float4* __restrict__ x,
                                             const int* __restrict__ list,
                                             const float* __restrict__ inv,
                                             int base, int deg, int f2,
                                             float4& a0, float4& a1) {
    int j = 0;
    for (; j + 8 <= deg; j += 8) {
        int   s[8];
        float w[8];
        #pragma unroll
        for (int u = 0; u < 8; u++) s[u] = __ldg(list + base + j + u);
        #pragma unroll
        for (int u = 0; u < 8; u++) w[u] = __ldg(inv + s[u]);
        #pragma unroll
        for (int u = 0; u < 8; u++) acc_edge(x, s[u], w[u], f2, a0, a1);
    }
    for (; j + 4 <= deg; j += 4) {
        int   s[4];
        float w[4];
        #pragma unroll
        for (int u = 0; u < 4; u++) s[u] = __ldg(list + base + j + u);
        #pragma unroll
        for (int u = 0; u < 4; u++) w[u] = __ldg(inv + s[u]);
        #pragma unroll
        for (int u = 0; u < 4; u++) acc_edge(x, s[u], w[u], f2, a0, a1);
    }
    for (; j < deg; j++) {
        int s = __ldg(list + base + j);
        float w = __ldg(inv + s);
        acc_edge(x, s, w, f2, a0, a1);
    }
}

__global__ void __launch_bounds__(256)
gather_agg_kernel(const float4* __restrict__ x,
                  const int* __restrict__ list,
                  const int* __restrict__ start,
                  const int* __restrict__ cnt,
                  const float* __restrict__ inv,
                  float4* __restrict__ agg, int n) {
    int t = blockIdx.x * blockDim.x + threadIdx.x;
    int node = t >> 3, f2 = (t & 7) * 2;
    if (node >= n) return;
    float4 a0 = make_float4(0.f, 0.f, 0.f, 0.f);
    float4 a1 = make_float4(0.f, 0.f, 0.f, 0.f);
    gather_range(x, list, inv, start[node], cnt[node], f2, a0, a1);
    agg[(size_t)node * FEAT4 + f2]     = a0;
    agg[(size_t)node * FEAT4 + f2 + 1] = a1;
}

__global__ void __launch_bounds__(256)
gather_agg_undirected_kernel(const float4* __restrict__ x,
                             const float* __restrict__ inv,
                             float4* __restrict__ agg, int n) {
    int t = blockIdx.x * blockDim.x + threadIdx.x;
    int node = t >> 3, f2 = (t & 7) * 2;
    if (node >= n) return;
    float4 a0 = make_float4(0.f, 0.f, 0.f, 0.f);
    float4 a1 = make_float4(0.f, 0.f, 0.f, 0.f);
    gather_range(x, g_in_list,  inv, g_start_in[node],  g_cnt_in[node],  f2, a0, a1);
    gather_range(x, g_out_list, inv, g_start_out[node], g_cnt_out[node], f2, a0, a1);
    agg[(size_t)node * FEAT4 + f2]     = a0;
    agg[(size_t)node * FEAT4 + f2 + 1] = a1;
}

// ---------------------------------------------------------------------------
// Fused concat-GEMM + bias + optional ReLU. Packed fma.rn.f32x2,
// 2 rows/thread, software-pipelined x/agg loads (prefetch 1 iteration ahead,
// including across the x -> agg half boundary).
// ---------------------------------------------------------------------------
__device__ __forceinline__ void fma2(unsigned long long& d,
                                     unsigned long long a,
                                     unsigned long long b) {
    asm("fma.rn.f32x2 %0, %1, %2, %0;" : "+l"(d) : "l"(a), "l"(b));
}
__device__ __forceinline__ unsigned long long pack2(float lo, float hi) {
    unsigned long long r;
    asm("mov.b64 %0, {%1, %2};" : "=l"(r) : "f"(lo), "f"(hi));
    return r;
}
__device__ __forceinline__ void unpack2(unsigned long long v, float& lo, float& hi) {
    asm("mov.b64 {%0, %1}, %2;" : "=f"(lo), "=f"(hi) : "l"(v));
}

__global__ void __launch_bounds__(128)
sage_gemm_kernel(const float4* __restrict__ x,
                 const float4* __restrict__ agg,
                 const float*  __restrict__ W,
                 const float*  __restrict__ b,
                 float* __restrict__ out,
                 int n, int relu) {
    __shared__ float4 Ws[128 * FEAT4];   // [k=128][col4=16] -> 32 KB
    __shared__ float  bs[FEAT];

    int tid = threadIdx.x;
    const float4* W4 = (const float4*)W;
    #pragma unroll
    for (int i = 0; i < 16; i++)
        Ws[tid + 128 * i] = W4[tid + 128 * i];
    if (tid < FEAT) bs[tid] = b[tid];
    __syncthreads();

    int r0 = blockIdx.x * 256 + tid;
    int r1 = r0 + 128;
    bool has0 = (r0 < n), has1 = (r1 < n);
    if (!has0) return;

    unsigned long long accA[32], accB[32];
    #pragma unroll
    for (int j = 0; j < 32; j++) {
        accA[j] = pack2(bs[2 * j], bs[2 * j + 1]);
        accB[j] = accA[j];
    }

    const float4* inA[2] = { x + (size_t)r0 * FEAT4, agg + (size_t)r0 * FEAT4 };
    const float4* inB[2] = { x + (size_t)r1 * FEAT4, agg + (size_t)r1 * FEAT4 };
    const float4 zero4 = make_float4(0.f, 0.f, 0.f, 0.f);

    float4 xa_n = __ldg(inA[0]);
    float4 xb_n = has1 ? __ldg(inB[0]) : zero4;

    #pragma unroll 1
    for (int half = 0; half < 2; half++) {
        const float4* wbase = Ws + half * 64 * FEAT4;
        #pragma unroll 2
        for (int k4 = 0; k4 < 16; k4++) {
            float4 xa = xa_n;
            float4 xb = xb_n;
            // Prefetch the next iteration's inputs (crossing into agg at k4==15).
            bool last = (half == 1) && (k4 == 15);
            if (!last) {
                const float4* nA = (k4 < 15) ? (inA[half] + k4 + 1) : inA[1];
                const float4* nB = (k4 < 15) ? (inB[half] + k4 + 1) : inB[1];
                xa_n = __ldg(nA);
                xb_n = has1 ? __ldg(nB) : zero4;
            }
            const float4* wr = wbase + k4 * 4 * FEAT4;
            #pragma unroll
            for (int c = 0; c < 4; c++) {
                float sa = (c == 0) ? xa.x : (c == 1) ? xa.y : (c == 2) ? xa.z : xa.w;
                float sb = (c == 0) ? xb.x : (c == 1) ? xb.y : (c == 2) ? xb.z : xb.w;
                unsigned long long sa2 = pack2(sa, sa);
                unsigned long long sb2 = pack2(sb, sb);
                const ulonglong2* wr2 = (const ulonglong2*)(wr + c * FEAT4);
                #pragma unroll
                for (int j = 0; j < 16; j++) {
                    ulonglong2 w = wr2[j];
                    fma2(accA[2 * j],     sa2, w.x);
                    fma2(accA[2 * j + 1], sa2, w.y);
                    fma2(accB[2 * j],     sb2, w.x);
                    fma2(accB[2 * j + 1], sb2, w.y);
                }
            }
        }
    }

    {
        float4* o = (float4*)(out + (size_t)r0 * FEAT);
        #pragma unroll
        for (int j4 = 0; j4 < FEAT4; j4++) {
            float4 v;
            unpack2(accA[2 * j4],     v.x, v.y);
            unpack2(accA[2 * j4 + 1], v.z, v.w);
            if (relu) {
                v.x = fmaxf(v.x, 0.f); v.y = fmaxf(v.y, 0.f);
                v.z = fmaxf(v.z, 0.f); v.w = fmaxf(v.w, 0.f);
            }
            o[j4] = v;
        }
    }
    if (has1) {
        float4* o = (float4*)(out + (size_t)r1 * FEAT);
        #pragma unroll
        for (int j4 = 0; j4 < FEAT4; j4++) {
            float4 v;
            unpack2(accB[2 * j4],     v.x, v.y);
            unpack2(accB[2 * j4 + 1], v.z, v.w);
            if (relu) {
                v.x = fmaxf(v.x, 0.f); v.y = fmaxf(v.y, 0.f);
                v.z = fmaxf(v.z, 0.f); v.w = fmaxf(v.w, 0.f);
            }
            o[j4] = v;
        }
    }
}

// ---------------------------------------------------------------------------
// Launch
// ---------------------------------------------------------------------------
extern "C" void kernel_launch(void* const* d_in, const int* in_sizes, int n_in,
                              void* d_out, int out_size) {
    const float* x   = (const float*)d_in[0];
    const int*   src = (const int*)  d_in[1];
    const int*   dst = (const int*)  d_in[2];
    const float* W1  = (const float*)d_in[3];
    const float* b1  = (const float*)d_in[4];
    const float* W2  = (const float*)d_in[5];
    const float* b2  = (const float*)d_in[6];
    const float* W3  = (const float*)d_in[7];
    const float* b3  = (const float*)d_in[8];
    float* out = (float*)d_out;

    int n = in_sizes[0] / FEAT;   // 100000
    int e = in_sizes[1];          // 1000000

    void *p_agg, *p_h1, *p_h2, *p_inv1, *p_inv2, *p_inv3;
    void *p_cnt_in, *p_cnt_out, *p_start_in, *p_start_out;
    void *p_in_list, *p_out_list;
    cudaGetSymbolAddress(&p_agg,       g_agg);
    cudaGetSymbolAddress(&p_h1,        g_h1);
    cudaGetSymbolAddress(&p_h2,        g_h2);
    cudaGetSymbolAddress(&p_inv1,      g_inv1);
    cudaGetSymbolAddress(&p_inv2,      g_inv2);
    cudaGetSymbolAddress(&p_inv3,      g_inv3);
    cudaGetSymbolAddress(&p_cnt_in,    g_cnt_in);
    cudaGetSymbolAddress(&p_cnt_out,   g_cnt_out);
    cudaGetSymbolAddress(&p_start_in,  g_start_in);
    cudaGetSymbolAddress(&p_start_out, g_start_out);
    cudaGetSymbolAddress(&p_in_list,   g_in_list);
    cudaGetSymbolAddress(&p_out_list,  g_out_list);

    float4* agg4 = (float4*)p_agg;
    float*  h1   = (float*)p_h1;
    float*  h2   = (float*)p_h2;

    const int TB = 256;
    int nb_e   = (e + TB - 1) / TB;
    int nb_s   = (n + SCAN_B - 1) / SCAN_B;
    int gt     = n << 3;                    // 8 threads per node
    int nb_g8  = (gt + TB - 1) / TB;
    int nb_g   = (n + 255) / 256;           // 2 rows/thread, 128 threads

    // --- CSR build ---
    cudaMemsetAsync(p_cnt_in,  0, (size_t)n * sizeof(int));
    cudaMemsetAsync(p_cnt_out, 0, (size_t)n * sizeof(int));
    count_deg_kernel<<<nb_e, TB>>>(src, dst, e);
    {
        dim3 g(nb_s, 2);
        scan_block2_kernel<<<g, SCAN_B>>>(n);
    }
    scan_sums_kernel<<<2, 128>>>(nb_s);
    add_offsets_inv_kernel<<<nb_s, SCAN_B>>>(n);
    fill_lists_kernel<<<nb_e, TB>>>(src, dst, e);

    // --- Layer 1: 'O' ---
    gather_agg_kernel<<<nb_g8, TB>>>((const float4*)x, (const int*)p_in_list,
                                     (const int*)p_start_in, (const int*)p_cnt_in,
                                     (const float*)p_inv1, agg4, n);
    sage_gemm_kernel<<<nb_g, 128>>>((const float4*)x, agg4, W1, b1, h1, n, 1);

    // --- Layer 2: 'I' ---
    gather_agg_kernel<<<nb_g8, TB>>>((const float4*)h1, (const int*)p_out_list,
                                     (const int*)p_start_out, (const int*)p_cnt_out,
                                     (const float*)p_inv2, agg4, n);
    sage_gemm_kernel<<<nb_g, 128>>>((const float4*)h1, agg4, W2, b2, h2, n, 1);

    // --- Layer 3: 'U' ---
    gather_agg_undirected_kernel<<<nb_g8, TB>>>((const float4*)h2,
                                                (const float*)p_inv3, agg4, n);
    sage_gemm_kernel<<<nb_g, 128>>>((const float4*)h2, agg4, W3, b3, out, n, 0);

    (void)n_in; (void)out_size;
}

// round 8
// speedup vs baseline: 1.9431x; 1.3657x over previous
#include <cuda_runtime.h>
#include <cuda_bf16.h>
#include <cstdint>

// Problem constants: N=100000 nodes, E=1000000 edges, F=64.
#define NMAX 100000
#define EMAX 1000000
#define FEAT 64
#define FEAT4 16
#define SCAN_B 1024
#define NBLK_SCAN ((NMAX + SCAN_B - 1) / SCAN_B)   // 98
#define WT_STRIDE 136   // padded bf16 per row in smem (68 words = 4 mod 32 banks)

// ---------------------------------------------------------------------------
// Device-global scratch
// ---------------------------------------------------------------------------
__device__ int   g_cnt_out[NMAX];
__device__ int   g_cnt_in [NMAX];
__device__ float g_inv1[NMAX];
__device__ float g_inv2[NMAX];
__device__ float g_inv3[NMAX];
__device__ int   g_start_in [NMAX];
__device__ int   g_start_out[NMAX];
__device__ int   g_cur_in [NMAX];
__device__ int   g_cur_out[NMAX];
__device__ int   g_bsum_in [NBLK_SCAN];
__device__ int   g_bsum_out[NBLK_SCAN];
__device__ int   g_in_list [EMAX];
__device__ int   g_out_list[EMAX];
__device__ float g_agg[(size_t)NMAX * FEAT];
__device__ float g_h1 [(size_t)NMAX * FEAT];
__device__ float g_h2 [(size_t)NMAX * FEAT];
// W transposed to WT[n=64][k=128], split bf16 hi/lo, plain row-major.
__device__ __align__(16) __nv_bfloat16 g_Whi[3][64 * 128];
__device__ __align__(16) __nv_bfloat16 g_Wlo[3][64 * 128];

// ---------------------------------------------------------------------------
// W conversion: WT[n][k] = W[k][n], bf16 hi + residual lo
// ---------------------------------------------------------------------------
__global__ void convert_w_kernel(const float* __restrict__ W1,
                                 const float* __restrict__ W2,
                                 const float* __restrict__ W3) {
    int i = blockIdx.x * blockDim.x + threadIdx.x;
    if (i < 3 * 64 * 128) {
        int m = i >> 13;
        int r = i & 8191;
        int nn = r >> 7;     // 0..63  output col
        int k  = r & 127;    // 0..127 input dim
        const float* W = (m == 0) ? W1 : (m == 1) ? W2 : W3;
        float v = W[k * 64 + nn];
        __nv_bfloat16 h = __float2bfloat16(v);
        __nv_bfloat16 l = __float2bfloat16(v - __bfloat162float(h));
        g_Whi[m][nn * 128 + k] = h;
        g_Wlo[m][nn * 128 + k] = l;
    }
}

// ---------------------------------------------------------------------------
// CSR build (identical to the 344us passing version)
// ---------------------------------------------------------------------------
__global__ void count_deg_kernel(const int* __restrict__ src,
                                 const int* __restrict__ dst, int e) {
    int i = blockIdx.x * blockDim.x + threadIdx.x;
    if (i < e) {
        atomicAdd(&g_cnt_out[src[i]], 1);
        atomicAdd(&g_cnt_in [dst[i]], 1);
    }
}

__global__ void scan_block2_kernel(int n) {
    __shared__ int sh[SCAN_B];
    const int* in  = (blockIdx.y == 0) ? g_cnt_in  : g_cnt_out;
    int* out   = (blockIdx.y == 0) ? g_start_in : g_start_out;
    int* bsums = (blockIdx.y == 0) ? g_bsum_in  : g_bsum_out;
    int tid = threadIdx.x;
    int gid = blockIdx.x * SCAN_B + tid;
    int v = (gid < n) ? in[gid] : 0;
    sh[tid] = v;
    __syncthreads();
    int acc = v;
    #pragma unroll
    for (int off = 1; off < SCAN_B; off <<= 1) {
        int add = (tid >= off) ? sh[tid - off] : 0;
        __syncthreads();
        acc += add;
        sh[tid] = acc;
        __syncthreads();
    }
    if (gid < n) out[gid] = acc - v;
    if (tid == SCAN_B - 1) bsums[blockIdx.x] = acc;
}

__global__ void scan_sums_kernel(int nb) {
    __shared__ int sh[128];
    int* b = (blockIdx.x == 0) ? g_bsum_in : g_bsum_out;
    int tid = threadIdx.x;
    int v = (tid < nb) ? b[tid] : 0;
    sh[tid] = v;
    __syncthreads();
    int acc = v;
    #pragma unroll
    for (int off = 1; off < 128; off <<= 1) {
        int add = (tid >= off) ? sh[tid - off] : 0;
        __syncthreads();
        acc += add;
        sh[tid] = acc;
        __syncthreads();
    }
    if (tid < nb) b[tid] = acc - v;
}

__global__ void add_offsets_inv_kernel(int n) {
    int gid = blockIdx.x * SCAN_B + threadIdx.x;
    if (gid < n) {
        int si = g_start_in[gid]  + g_bsum_in [blockIdx.x];
        int so = g_start_out[gid] + g_bsum_out[blockIdx.x];
        g_start_in[gid]  = si;  g_cur_in[gid]  = si;
        g_start_out[gid] = so;  g_cur_out[gid] = so;
        int co = g_cnt_out[gid];
        int ci = g_cnt_in[gid];
        g_inv1[gid] = 1.0f / (float)(co > 0 ? co : 1);
        g_inv2[gid] = 1.0f / (float)(ci > 0 ? ci : 1);
        int cu = co + ci;
        g_inv3[gid] = 1.0f / (float)(cu > 0 ? cu : 1);
    }
}

__global__ void fill_lists_kernel(const int* __restrict__ src,
                                  const int* __restrict__ dst, int e) {
    int i = blockIdx.x * blockDim.x + threadIdx.x;
    if (i < e) {
        int s = src[i], d = dst[i];
        int p1 = atomicAdd(&g_cur_in[d], 1);
        g_in_list[p1] = s;
        int p2 = atomicAdd(&g_cur_out[s], 1);
        g_out_list[p2] = d;
    }
}

// ---------------------------------------------------------------------------
// Gather aggregation (identical to 344us passing version)
// ---------------------------------------------------------------------------
__device__ __forceinline__ void acc_edge(const float4* __restrict__ x,
                                         int s, float iw, int f2,
                                         float4& a0, float4& a1) {
    float4 v0 = __ldg(x + (size_t)s * FEAT4 + f2);
    float4 v1 = __ldg(x + (size_t)s * FEAT4 + f2 + 1);
    a0.x += v0.x * iw; a0.y += v0.y * iw; a0.z += v0.z * iw; a0.w += v0.w * iw;
    a1.x += v1.x * iw; a1.y += v1.y * iw; a1.z += v1.z * iw; a1.w += v1.w * iw;
}

__device__ __forceinline__ void gather_range(const float4* __restrict__ x,
                                             const int* __restrict__ list,
                                             const float* __restrict__ inv,
                                             int base, int deg, int f2,
                                             float4& a0, float4& a1) {
    int j = 0;
    for (; j + 8 <= deg; j += 8) {
        int s[8]; float w[8];
        #pragma unroll
        for (int u = 0; u < 8; u++) s[u] = __ldg(list + base + j + u);
        #pragma unroll
        for (int u = 0; u < 8; u++) w[u] = __ldg(inv + s[u]);
        #pragma unroll
        for (int u = 0; u < 8; u++) acc_edge(x, s[u], w[u], f2, a0, a1);
    }
    for (; j + 4 <= deg; j += 4) {
        int s[4]; float w[4];
        #pragma unroll
        for (int u = 0; u < 4; u++) s[u] = __ldg(list + base + j + u);
        #pragma unroll
        for (int u = 0; u < 4; u++) w[u] = __ldg(inv + s[u]);
        #pragma unroll
        for (int u = 0; u < 4; u++) acc_edge(x, s[u], w[u], f2, a0, a1);
    }
    for (; j < deg; j++) {
        int s = __ldg(list + base + j);
        float w = __ldg(inv + s);
        acc_edge(x, s, w, f2, a0, a1);
    }
}

__global__ void __launch_bounds__(256)
gather_agg_kernel(const float4* __restrict__ x,
                  const int* __restrict__ list,
                  const int* __restrict__ start,
                  const int* __restrict__ cnt,
                  const float* __restrict__ inv,
                  float4* __restrict__ agg, int n) {
    int t = blockIdx.x * blockDim.x + threadIdx.x;
    int node = t >> 3, f2 = (t & 7) * 2;
    if (node >= n) return;
    float4 a0 = make_float4(0.f, 0.f, 0.f, 0.f);
    float4 a1 = make_float4(0.f, 0.f, 0.f, 0.f);
    gather_range(x, list, inv, start[node], cnt[node], f2, a0, a1);
    agg[(size_t)node * FEAT4 + f2]     = a0;
    agg[(size_t)node * FEAT4 + f2 + 1] = a1;
}

__global__ void __launch_bounds__(256)
gather_agg_undirected_kernel(const float4* __restrict__ x,
                             const float* __restrict__ inv,
                             float4* __restrict__ agg, int n) {
    int t = blockIdx.x * blockDim.x + threadIdx.x;
    int node = t >> 3, f2 = (t & 7) * 2;
    if (node >= n) return;
    float4 a0 = make_float4(0.f, 0.f, 0.f, 0.f);
    float4 a1 = make_float4(0.f, 0.f, 0.f, 0.f);
    gather_range(x, g_in_list,  inv, g_start_in[node],  g_cnt_in[node],  f2, a0, a1);
    gather_range(x, g_out_list, inv, g_start_out[node], g_cnt_out[node], f2, a0, a1);
    agg[(size_t)node * FEAT4 + f2]     = a0;
    agg[(size_t)node * FEAT4 + f2 + 1] = a1;
}

// ---------------------------------------------------------------------------
// Tensor-core GEMM (mma.sync m16n8k16 bf16, sm_80+ path — works on sm_100):
//   D(f32) = Ahi*Bhi + Alo*Bhi + Ahi*Blo,  A = [x|agg] fp32 split in regs,
//   B = WT hi/lo staged in padded smem.  out = act(D + bias).
// CTA: 128 threads = 4 warps, 128 rows. Warp: 32 rows (2 m16) x 64 cols (8 n8).
// ---------------------------------------------------------------------------
__device__ __forceinline__ void mma16816(float* c, const uint32_t* a, const uint32_t* b) {
    asm volatile(
        "mma.sync.aligned.m16n8k16.row.col.f32.bf16.bf16.f32 "
        "{%0,%1,%2,%3}, {%4,%5,%6,%7}, {%8,%9}, {%0,%1,%2,%3};"
        : "+f"(c[0]), "+f"(c[1]), "+f"(c[2]), "+f"(c[3])
        : "r"(a[0]), "r"(a[1]), "r"(a[2]), "r"(a[3]), "r"(b[0]), "r"(b[1]));
}

__device__ __forceinline__ void split2(float2 v, uint32_t& hi, uint32_t& lo) {
    __nv_bfloat16 hx = __float2bfloat16(v.x);
    __nv_bfloat16 hy = __float2bfloat16(v.y);
    __nv_bfloat162 h2 = __halves2bfloat162(hx, hy);          // .x -> low 16 bits
    hi = *(uint32_t*)&h2;
    __nv_bfloat162 l2 = __halves2bfloat162(
        __float2bfloat16(v.x - __bfloat162float(hx)),
        __float2bfloat16(v.y - __bfloat162float(hy)));
    lo = *(uint32_t*)&l2;
}

__global__ void __launch_bounds__(128)
mma_layer_kernel(const float* __restrict__ x,
                 const float* __restrict__ agg,
                 const __nv_bfloat16* __restrict__ WThi,
                 const __nv_bfloat16* __restrict__ WTlo,
                 const float* __restrict__ bias,
                 float* __restrict__ out, int n, int relu) {
    __shared__ __nv_bfloat16 sWhi[64 * WT_STRIDE];
    __shared__ __nv_bfloat16 sWlo[64 * WT_STRIDE];

    int tid  = threadIdx.x;
    int wid  = tid >> 5;
    int lane = tid & 31;
    int gid  = lane >> 2;    // groupID 0..7
    int tg   = lane & 3;     // 0..3

    // Stage WT [64][128] bf16 into padded smem rows (WT_STRIDE/2 = 68 words)
    {
        const uint32_t* sh = (const uint32_t*)WThi;
        const uint32_t* sl = (const uint32_t*)WTlo;
        uint32_t* dh = (uint32_t*)sWhi;
        uint32_t* dl = (uint32_t*)sWlo;
        #pragma unroll
        for (int i = tid; i < 64 * 64; i += 128) {
            int row = i >> 6, col = i & 63;
            dh[row * (WT_STRIDE / 2) + col] = __ldg(sh + i);
            dl[row * (WT_STRIDE / 2) + col] = __ldg(sl + i);
        }
    }
    __syncthreads();

    int row0 = blockIdx.x * 128 + wid * 32;
    float acc[2][8][4];
    #pragma unroll
    for (int mt = 0; mt < 2; mt++)
        #pragma unroll
        for (int nt = 0; nt < 8; nt++)
            #pragma unroll
            for (int c = 0; c < 4; c++) acc[mt][nt][c] = 0.f;

    const float2 z2 = make_float2(0.f, 0.f);

    #pragma unroll 1
    for (int kt = 0; kt < 8; kt++) {
        int k0 = kt * 16;
        const float* base = (k0 < 64) ? (x + k0) : (agg + (k0 - 64));
        uint32_t ahi[2][4], alo[2][4];
        #pragma unroll
        for (int mt = 0; mt < 2; mt++) {
            int ra = row0 + mt * 16 + gid;      // rows gid and gid+8
            int rb = ra + 8;
            bool va = ra < n, vb = rb < n;
            const float* pa = base + (size_t)ra * FEAT + tg * 2;
            const float* pb = base + (size_t)rb * FEAT + tg * 2;
            float2 v00 = va ? __ldg((const float2*)pa)       : z2;  // a0: row gid,  k lo
            float2 v01 = va ? __ldg((const float2*)(pa + 8)) : z2;  // a2: row gid,  k hi
            float2 v10 = vb ? __ldg((const float2*)pb)       : z2;  // a1: row gid+8, k lo
            float2 v11 = vb ? __ldg((const float2*)(pb + 8)) : z2;  // a3: row gid+8, k hi
            split2(v00, ahi[mt][0], alo[mt][0]);
            split2(v10, ahi[mt][1], alo[mt][1]);
            split2(v01, ahi[mt][2], alo[mt][2]);
            split2(v11, ahi[mt][3], alo[mt][3]);
        }
        #pragma unroll
        for (int nt = 0; nt < 8; nt++) {
            int brow = nt * 8 + gid;
            const __nv_bfloat16* ph = sWhi + brow * WT_STRIDE + k0 + tg * 2;
            const __nv_bfloat16* pl = sWlo + brow * WT_STRIDE + k0 + tg * 2;
            uint32_t bhi[2], blo[2];
            bhi[0] = *(const uint32_t*)ph;
            bhi[1] = *(const uint32_t*)(ph + 8);
            blo[0] = *(const uint32_t*)pl;
            blo[1] = *(const uint32_t*)(pl + 8);
            #pragma unroll
            for (int mt = 0; mt < 2; mt++) {
                mma16816(acc[mt][nt], ahi[mt], bhi);
                mma16816(acc[mt][nt], alo[mt], bhi);
                mma16816(acc[mt][nt], ahi[mt], blo);
            }
        }
    }

    // Epilogue: c0,c1 -> row gid, cols tg*2..+1 ; c2,c3 -> row gid+8
    #pragma unroll
    for (int mt = 0; mt < 2; mt++) {
        int ra = row0 + mt * 16 + gid;
        int rb = ra + 8;
        #pragma unroll
        for (int nt = 0; nt < 8; nt++) {
            int c0 = nt * 8 + tg * 2;
            float2 bv = __ldg((const float2*)(bias + c0));
            float2 o0 = make_float2(acc[mt][nt][0] + bv.x, acc[mt][nt][1] + bv.y);
            float2 o1 = make_float2(acc[mt][nt][2] + bv.x, acc[mt][nt][3] + bv.y);
            if (relu) {
                o0.x = fmaxf(o0.x, 0.f); o0.y = fmaxf(o0.y, 0.f);
                o1.x = fmaxf(o1.x, 0.f); o1.y = fmaxf(o1.y, 0.f);
            }
            if (ra < n) *(float2*)(out + (size_t)ra * FEAT + c0) = o0;
            if (rb < n) *(float2*)(out + (size_t)rb * FEAT + c0) = o1;
        }
    }
}

// ---------------------------------------------------------------------------
// Launch
// ---------------------------------------------------------------------------
extern "C" void kernel_launch(void* const* d_in, const int* in_sizes, int n_in,
                              void* d_out, int out_size) {
    const float* x   = (const float*)d_in[0];
    const int*   src = (const int*)  d_in[1];
    const int*   dst = (const int*)  d_in[2];
    const float* W1  = (const float*)d_in[3];
    const float* b1  = (const float*)d_in[4];
    const float* W2  = (const float*)d_in[5];
    const float* b2  = (const float*)d_in[6];
    const float* W3  = (const float*)d_in[7];
    const float* b3  = (const float*)d_in[8];
    float* out = (float*)d_out;

    int n = in_sizes[0] / FEAT;   // 100000
    int e = in_sizes[1];          // 1000000

    void *p_agg, *p_h1, *p_h2, *p_inv1, *p_inv2, *p_inv3;
    void *p_cnt_in, *p_cnt_out, *p_start_in, *p_start_out;
    void *p_in_list, *p_out_list, *p_whi, *p_wlo;
    cudaGetSymbolAddress(&p_agg,       g_agg);
    cudaGetSymbolAddress(&p_h1,        g_h1);
    cudaGetSymbolAddress(&p_h2,        g_h2);
    cudaGetSymbolAddress(&p_inv1,      g_inv1);
    cudaGetSymbolAddress(&p_inv2,      g_inv2);
    cudaGetSymbolAddress(&p_inv3,      g_inv3);
    cudaGetSymbolAddress(&p_cnt_in,    g_cnt_in);
    cudaGetSymbolAddress(&p_cnt_out,   g_cnt_out);
    cudaGetSymbolAddress(&p_start_in,  g_start_in);
    cudaGetSymbolAddress(&p_start_out, g_start_out);
    cudaGetSymbolAddress(&p_in_list,   g_in_list);
    cudaGetSymbolAddress(&p_out_list,  g_out_list);
    cudaGetSymbolAddress(&p_whi,       g_Whi);
    cudaGetSymbolAddress(&p_wlo,       g_Wlo);

    float4* agg4 = (float4*)p_agg;
    float*  h1   = (float*)p_h1;
    float*  h2   = (float*)p_h2;
    const __nv_bfloat16* Whi = (const __nv_bfloat16*)p_whi;
    const __nv_bfloat16* Wlo = (const __nv_bfloat16*)p_wlo;

    const int TB = 256;
    int nb_e  = (e + TB - 1) / TB;
    int nb_s  = (n + SCAN_B - 1) / SCAN_B;
    int gt    = n << 3;
    int nb_g8 = (gt + TB - 1) / TB;
    int ntile = (n + 127) / 128;

    // --- CSR build + W convert ---
    cudaMemsetAsync(p_cnt_in,  0, (size_t)n * sizeof(int));
    cudaMemsetAsync(p_cnt_out, 0, (size_t)n * sizeof(int));
    convert_w_kernel<<<(3 * 64 * 128 + TB - 1) / TB, TB>>>(W1, W2, W3);
    count_deg_kernel<<<nb_e, TB>>>(src, dst, e);
    {
        dim3 g(nb_s, 2);
        scan_block2_kernel<<<g, SCAN_B>>>(n);
    }
    scan_sums_kernel<<<2, 128>>>(nb_s);
    add_offsets_inv_kernel<<<nb_s, SCAN_B>>>(n);
    fill_lists_kernel<<<nb_e, TB>>>(src, dst, e);

    // --- Layer 1: 'O' ---
    gather_agg_kernel<<<nb_g8, TB>>>((const float4*)x, (const int*)p_in_list,
                                     (const int*)p_start_in, (const int*)p_cnt_in,
                                     (const float*)p_inv1, agg4, n);
    mma_layer_kernel<<<ntile, 128>>>(x, (const float*)p_agg, Whi, Wlo, b1, h1, n, 1);

    // --- Layer 2: 'I' ---
    gather_agg_kernel<<<nb_g8, TB>>>((const float4*)h1, (const int*)p_out_list,
                                     (const int*)p_start_out, (const int*)p_cnt_out,
                                     (const float*)p_inv2, agg4, n);
    mma_layer_kernel<<<ntile, 128>>>(h1, (const float*)p_agg, Whi + 64 * 128, Wlo + 64 * 128, b2, h2, n, 1);

    // --- Layer 3: 'U' ---
    gather_agg_undirected_kernel<<<nb_g8, TB>>>((const float4*)h2,
                                                (const float*)p_inv3, agg4, n);
    mma_layer_kernel<<<ntile, 128>>>(h2, (const float*)p_agg, Whi + 2 * 64 * 128, Wlo + 2 * 64 * 128, b3, out, n, 0);

    (void)n_in; (void)out_size;
}